// round 6
// baseline (speedup 1.0000x reference)
#include <cuda_runtime.h>
#include <cstdint>

#define IN_DIM  16
#define OUT_DIM 32
#define BLOCK   256

// Launch-invariant precomputed state (written by prep kernel each launch).
__device__ uint4  g_wp[OUT_DIM];     // plus-plane  bytes {0,1}, one u32 per group
__device__ uint4  g_wm[OUT_DIM];     // minus-plane bytes {0,1}
__device__ float  g_bias2[OUT_DIM];  // in_min*sum(sign) - rng*count(minus)
__device__ float  g_cs1;             // 1 / rng
__device__ float  g_cs0;             // -in_min / rng
__device__ float  g_rng;             // in_max - in_min

__global__ void prep_kernel(const float* __restrict__ weight,
                            const float* __restrict__ in_max_p,
                            const float* __restrict__ in_min_p) {
    int o = threadIdx.x;
    float in_min = in_min_p[0];
    float rng = in_max_p[0] - in_min;
    if (o == 0) {
        g_rng = rng;
        g_cs1 = 1.0f / rng;
        g_cs0 = -in_min / rng;
    }
    if (o < OUT_DIM) {
        unsigned p[4] = {0u, 0u, 0u, 0u};
        unsigned m[4] = {0u, 0u, 0u, 0u};
        int S = 0, MC = 0;
        #pragma unroll
        for (int i = 0; i < IN_DIM; i++) {
            float wf = weight[o * IN_DIM + i];
            int s = (wf > 0.0f) - (wf < 0.0f);
            S += s;
            if (s < 0) MC++;
            int g = i >> 2, k = i & 3;
            if (s > 0) p[g] |= 1u << (8 * k);
            if (s < 0) m[g] |= 1u << (8 * k);
        }
        g_wp[o] = make_uint4(p[0], p[1], p[2], p[3]);
        g_wm[o] = make_uint4(m[0], m[1], m[2], m[3]);
        // out = (Sum rt_p + Sum rt15(15*mc - ym)) * rng + (in_min*S - rng*MC)
        g_bias2[o] = in_min * (float)S - rng * (float)MC;
    }
}

__device__ __forceinline__ unsigned quant4(float v, float cs1, float cs0) {
    // clip(round((x-in_min)/rng * 15), 0, 15) == round(saturate((x-in_min)/rng)*15)
    float f = __saturatef(fmaf(v, cs1, cs0));   // FFMA.SAT
    return __float2uint_rn(f * 15.0f);          // FMUL + F2I.RN
}

// Exact: round(y/15) = (y*17+128)>>8 for y in [0,60]; result lives in byte 1.
// Complement identity round(-ym/15) = rt15(15*mc - ym) - mc makes both planes
// additive; PRMT gathers the two rt bytes; bytes accumulate carry-free.

__global__ __launch_bounds__(BLOCK, 4)
void quantlinear_kernel(const float* __restrict__ x,
                        float* __restrict__ out) {
    const int t   = threadIdx.x & 31;
    const int wid = threadIdx.x >> 5;
    const int oc  = t & 7;             // output float4-chunk owned by this lane

    // ---- per-lane persistent weights + bias (coalesced one-time loads) ----
    uint4 WP[4], WM[4];
    #pragma unroll
    for (int jj = 0; jj < 4; jj++) {
        WP[jj] = g_wp[oc * 4 + jj];
        WM[jj] = g_wm[oc * 4 + jj];
    }
    const float4 BIAS2 = reinterpret_cast<const float4*>(g_bias2)[oc];
    const float cs1 = g_cs1;
    const float cs0 = g_cs0;
    const float rng = g_rng;

    const int wrow0 = (blockIdx.x * 8 + wid) * 32;
    const float4* __restrict__ xin  = reinterpret_cast<const float4*>(x);
    float4*       __restrict__ outf = reinterpret_cast<float4*>(out);

    #pragma unroll
    for (int k = 0; k < 4; k++) {
        // lane t holds (row = 8k + t>>2, group = t&3); quantize + byte-pack
        float4 v = xin[(wrow0 + 8 * k) * 4 + t];
        unsigned q0 = quant4(v.x, cs1, cs0);
        unsigned q1 = quant4(v.y, cs1, cs0);
        unsigned q2 = quant4(v.z, cs1, cs0);
        unsigned q3 = quant4(v.w, cs1, cs0);
        unsigned q  = __byte_perm(__byte_perm(q0, q1, 0x0040),
                                  __byte_perm(q2, q3, 0x0040), 0x5410);

        #pragma unroll
        for (int h = 0; h < 2; h++) {
            // lane t computes local row 4h + (t>>3); gather its 4 group words
            int src = 16 * h + (t >> 3) * 4;
            unsigned nq0 = __shfl_sync(0xffffffffu, q, src + 0);
            unsigned nq1 = __shfl_sync(0xffffffffu, q, src + 1);
            unsigned nq2 = __shfl_sync(0xffffffffu, q, src + 2);
            unsigned nq3 = __shfl_sync(0xffffffffu, q, src + 3);
            // nibble complement: 15 - q  (q has low nibbles only)
            unsigned nc0 = nq0 ^ 0x0f0f0f0fu;
            unsigned nc1 = nq1 ^ 0x0f0f0f0fu;
            unsigned nc2 = nq2 ^ 0x0f0f0f0fu;
            unsigned nc3 = nq3 ^ 0x0f0f0f0fu;

            float4 res;
            float* rp = reinterpret_cast<float*>(&res);
            const float* bp = reinterpret_cast<const float*>(&BIAS2);
            #pragma unroll
            for (int jj = 0; jj < 4; jj++) {
                const unsigned* wp = reinterpret_cast<const unsigned*>(&WP[jj]);
                const unsigned* wm = reinterpret_cast<const unsigned*>(&WM[jj]);

                unsigned yp0 = __dp4a(nq0, wp[0], 0u), ym0 = __dp4a(nc0, wm[0], 0u);
                unsigned yp1 = __dp4a(nq1, wp[1], 0u), ym1 = __dp4a(nc1, wm[1], 0u);
                unsigned yp2 = __dp4a(nq2, wp[2], 0u), ym2 = __dp4a(nc2, wm[2], 0u);
                unsigned yp3 = __dp4a(nq3, wp[3], 0u), ym3 = __dp4a(nc3, wm[3], 0u);

                unsigned p0 = __byte_perm(yp0 * 17u + 128u, ym0 * 17u + 128u, 0x3351);
                unsigned p1 = __byte_perm(yp1 * 17u + 128u, ym1 * 17u + 128u, 0x5133);
                unsigned p2 = __byte_perm(yp2 * 17u + 128u, ym2 * 17u + 128u, 0x3351);
                unsigned p3 = __byte_perm(yp3 * 17u + 128u, ym3 * 17u + 128u, 0x5133);

                unsigned V = (p0 + p1) + (p2 + p3);       // carry-free byte lanes
                int S = (int)__dp4a(V, 0x01010101u, 0u);  // sum of 8 rt values
                rp[jj] = fmaf((float)S, rng, bp[jj]);
            }
            // warp covers 4 rows x 128B contiguous -> fully coalesced STG.128
            outf[(wrow0 + 8 * k + 4 * h) * 8 + t] = res;
        }
    }
}

extern "C" void kernel_launch(void* const* d_in, const int* in_sizes, int n_in,
                              void* d_out, int out_size) {
    const float* x      = (const float*)d_in[0];
    const float* weight = (const float*)d_in[1];
    // d_in[2] = scale (unused in forward)
    const float* in_max = (const float*)d_in[3];
    const float* in_min = (const float*)d_in[4];
    float* out = (float*)d_out;

    int B = in_sizes[0] / IN_DIM;   // 2,097,152

    prep_kernel<<<1, 32>>>(weight, in_max, in_min);

    int blocks = B / BLOCK;         // 256 rows per block (8 warps x 32 rows)
    quantlinear_kernel<<<blocks, BLOCK>>>(x, out);
}

// round 7
// speedup vs baseline: 1.2765x; 1.2765x over previous
#include <cuda_runtime.h>
#include <cstdint>

#define IN_DIM  16
#define OUT_DIM 32
#define BLOCK   256

// Launch-invariant precomputed state (written by prep kernel each launch).
__device__ uint4  g_wp[OUT_DIM];    // plus-plane  bytes {0,1}, one u32 per group
__device__ uint4  g_wm[OUT_DIM];    // minus-plane bytes {0,1}
__device__ float  g_bias[OUT_DIM];  // in_min * sum_i sign(w[o,i])
__device__ float  g_cs1;            // 1 / rng
__device__ float  g_cs0;            // -in_min / rng
__device__ float  g_rng;            // in_max - in_min

__global__ void prep_kernel(const float* __restrict__ weight,
                            const float* __restrict__ in_max_p,
                            const float* __restrict__ in_min_p) {
    int o = threadIdx.x;
    float in_min = in_min_p[0];
    float rng = in_max_p[0] - in_min;
    if (o == 0) {
        g_rng = rng;
        g_cs1 = 1.0f / rng;
        g_cs0 = -in_min / rng;
    }
    if (o < OUT_DIM) {
        unsigned p[4] = {0u, 0u, 0u, 0u};
        unsigned m[4] = {0u, 0u, 0u, 0u};
        int S = 0;
        #pragma unroll
        for (int i = 0; i < IN_DIM; i++) {
            float wf = weight[o * IN_DIM + i];
            int s = (wf > 0.0f) - (wf < 0.0f);
            S += s;
            int g = i >> 2, k = i & 3;
            if (s > 0) p[g] |= 1u << (8 * k);
            if (s < 0) m[g] |= 1u << (8 * k);
        }
        g_wp[o] = make_uint4(p[0], p[1], p[2], p[3]);
        g_wm[o] = make_uint4(m[0], m[1], m[2], m[3]);
        g_bias[o] = in_min * (float)S;
    }
}

__device__ __forceinline__ unsigned quant4(float v, float cs1, float cs0) {
    // clip(round((x-in_min)/rng*15), 0, 15) == round(saturate((x-in_min)/rng)*15)
    float f = __saturatef(fmaf(v, cs1, cs0));   // FFMA.SAT
    return __float2uint_rn(f * 15.0f);          // FMUL + F2I.RN
}

// Exact: round(y/15) = byte1 of (y*17+128) for y in [0,60].
// round is odd on the attainable set (no exact halves), so
// terms = rt(yp) - rt(ym); PRMT packs rt_p in bytes{0,1}, rt_m in bytes{2,3};
// one signed dp4a with sel {+1,+1,-1,-1} and acc 0x4B400000 yields
// float-bits of (12582912 + S) directly (no I2F).

__global__ __launch_bounds__(BLOCK, 4)
void quantlinear_kernel(const float* __restrict__ x,
                        float* __restrict__ out) {
    const int t   = threadIdx.x & 31;
    const int wid = threadIdx.x >> 5;
    const int oc2 = t & 15;            // output float2-chunk owned by this lane

    // ---- per-lane persistent weights + bias (coalesced one-time loads) ----
    uint4 WP[2], WM[2];
    #pragma unroll
    for (int jj = 0; jj < 2; jj++) {
        WP[jj] = g_wp[oc2 * 2 + jj];
        WM[jj] = g_wm[oc2 * 2 + jj];
    }
    const float2 BIAS = reinterpret_cast<const float2*>(g_bias)[oc2];
    const float cs1 = g_cs1;
    const float cs0 = g_cs0;
    const float rng = g_rng;

    const int wrow0 = (blockIdx.x * 8 + wid) * 32;
    const float4* __restrict__ xin  = reinterpret_cast<const float4*>(x);
    float2*       __restrict__ out2 = reinterpret_cast<float2*>(out);

    #pragma unroll
    for (int k = 0; k < 4; k++) {
        // lane t holds (row = 8k + t>>2, group = t&3); quantize + byte-pack
        float4 v = xin[(wrow0 + 8 * k) * 4 + t];
        unsigned q0 = quant4(v.x, cs1, cs0);
        unsigned q1 = quant4(v.y, cs1, cs0);
        unsigned q2 = quant4(v.z, cs1, cs0);
        unsigned q3 = quant4(v.w, cs1, cs0);
        unsigned q  = __byte_perm(__byte_perm(q0, q1, 0x0040),
                                  __byte_perm(q2, q3, 0x0040), 0x5410);

        #pragma unroll
        for (int h = 0; h < 4; h++) {
            // lane t computes local row r = 2h + (t>>4); gather its 4 groups
            int r   = 2 * h + (t >> 4);
            int src = r * 4;
            unsigned nq0 = __shfl_sync(0xffffffffu, q, src + 0);
            unsigned nq1 = __shfl_sync(0xffffffffu, q, src + 1);
            unsigned nq2 = __shfl_sync(0xffffffffu, q, src + 2);
            unsigned nq3 = __shfl_sync(0xffffffffu, q, src + 3);

            float2 res;
            float* rp = reinterpret_cast<float*>(&res);
            const float* bp = reinterpret_cast<const float*>(&BIAS);
            #pragma unroll
            for (int jj = 0; jj < 2; jj++) {
                const unsigned* wp = reinterpret_cast<const unsigned*>(&WP[jj]);
                const unsigned* wm = reinterpret_cast<const unsigned*>(&WM[jj]);

                unsigned yp0 = __dp4a(nq0, wp[0], 0u), ym0 = __dp4a(nq0, wm[0], 0u);
                unsigned yp1 = __dp4a(nq1, wp[1], 0u), ym1 = __dp4a(nq1, wm[1], 0u);
                unsigned yp2 = __dp4a(nq2, wp[2], 0u), ym2 = __dp4a(nq2, wm[2], 0u);
                unsigned yp3 = __dp4a(nq3, wp[3], 0u), ym3 = __dp4a(nq3, wm[3], 0u);

                // {rt_p, 0, rt_m, 0} and {0, rt_p, 0, rt_m}
                unsigned p0 = __byte_perm(yp0 * 17u + 128u, ym0 * 17u + 128u, 0x7531);
                unsigned p1 = __byte_perm(yp1 * 17u + 128u, ym1 * 17u + 128u, 0x5713);
                unsigned p2 = __byte_perm(yp2 * 17u + 128u, ym2 * 17u + 128u, 0x7531);
                unsigned p3 = __byte_perm(yp3 * 17u + 128u, ym3 * 17u + 128u, 0x5713);

                unsigned V = (p0 + p1) + (p2 + p3);   // byte lanes, max 8 each
                // signed dp4a: +p bytes, -m bytes, acc = float-bias 2^23+2^22
                int Sb = __dp4a((int)V, (int)0xFFFF0101u, (int)0x4B400000);
                float Sf = __int_as_float(Sb) - 12582912.0f;   // exact S
                rp[jj] = fmaf(Sf, rng, bp[jj]);
            }
            // warp = 2 rows x 128B contiguous -> coalesced STG.64
            out2[(wrow0 + 8 * k + r) * 16 + oc2] = res;
        }
    }
}

extern "C" void kernel_launch(void* const* d_in, const int* in_sizes, int n_in,
                              void* d_out, int out_size) {
    const float* x      = (const float*)d_in[0];
    const float* weight = (const float*)d_in[1];
    // d_in[2] = scale (unused in forward)
    const float* in_max = (const float*)d_in[3];
    const float* in_min = (const float*)d_in[4];
    float* out = (float*)d_out;

    int B = in_sizes[0] / IN_DIM;   // 2,097,152

    prep_kernel<<<1, 32>>>(weight, in_max, in_min);

    int blocks = B / BLOCK;         // 256 rows per block (8 warps x 32 rows)
    quantlinear_kernel<<<blocks, BLOCK>>>(x, out);
}

// round 8
// speedup vs baseline: 1.4944x; 1.1708x over previous
#include <cuda_runtime.h>
#include <cstdint>

#define IN_DIM  16
#define OUT_DIM 32
#define BLOCK   256

// Launch-invariant precomputed state (written by prep kernel each launch).
// Weight planes are pre-scaled by 17 so dp4a(nq, w17, 128) = y*17+128 directly
// (max 60*17+128 = 1148, byte1 = round(y/15) exactly for y in [0,60]).
__device__ uint4  g_wp17[OUT_DIM];  // plus-plane  bytes {0,17}
__device__ uint4  g_wm17[OUT_DIM];  // minus-plane bytes {0,17}
__device__ float  g_bias[OUT_DIM];  // in_min * sum_i sign(w[o,i])
__device__ float  g_cs1;            // 1 / rng
__device__ float  g_cs0;            // -in_min / rng
__device__ float  g_rng;            // in_max - in_min

__global__ void prep_kernel(const float* __restrict__ weight,
                            const float* __restrict__ in_max_p,
                            const float* __restrict__ in_min_p) {
    int o = threadIdx.x;
    float in_min = in_min_p[0];
    float rng = in_max_p[0] - in_min;
    if (o == 0) {
        g_rng = rng;
        g_cs1 = 1.0f / rng;
        g_cs0 = -in_min / rng;
    }
    if (o < OUT_DIM) {
        unsigned p[4] = {0u, 0u, 0u, 0u};
        unsigned m[4] = {0u, 0u, 0u, 0u};
        int S = 0;
        #pragma unroll
        for (int i = 0; i < IN_DIM; i++) {
            float wf = weight[o * IN_DIM + i];
            int s = (wf > 0.0f) - (wf < 0.0f);
            S += s;
            int g = i >> 2, k = i & 3;
            if (s > 0) p[g] |= 17u << (8 * k);
            if (s < 0) m[g] |= 17u << (8 * k);
        }
        g_wp17[o] = make_uint4(p[0], p[1], p[2], p[3]);
        g_wm17[o] = make_uint4(m[0], m[1], m[2], m[3]);
        g_bias[o] = in_min * (float)S;
    }
}

__device__ __forceinline__ unsigned quant4(float v, float cs1, float cs0) {
    // clip(round((x-in_min)/rng*15), 0, 15) == round(saturate((x-in_min)/rng)*15)
    float f = __saturatef(fmaf(v, cs1, cs0));   // FFMA.SAT
    return __float2uint_rn(f * 15.0f);          // FMUL + F2I.RN
}

// rt(y) = byte1 of dp4a(q_group, w17, 128). round is odd on the attainable
// set (no exact halves), so terms = rt(yp) - rt(ym). PRMT packs rt_p into
// bytes {0,1} and rt_m into bytes {2,3}; bytes accumulate carry-free
// (max 16 < 256); one signed dp4a with sel {+1,+1,-1,-1} and accumulator
// 0x4B400000 yields float-bits of (12582912 + S) directly (no I2F).

__global__ __launch_bounds__(BLOCK, 4)
void quantlinear_kernel(const float* __restrict__ x,
                        float* __restrict__ out) {
    const int t   = threadIdx.x & 31;
    const int wid = threadIdx.x >> 5;
    const int oc2 = t & 15;            // output float2-chunk owned by this lane

    // ---- per-lane persistent weights + bias (coalesced one-time loads) ----
    uint4 WP[2], WM[2];
    #pragma unroll
    for (int jj = 0; jj < 2; jj++) {
        WP[jj] = g_wp17[oc2 * 2 + jj];
        WM[jj] = g_wm17[oc2 * 2 + jj];
    }
    const float2 BIAS = reinterpret_cast<const float2*>(g_bias)[oc2];
    const float cs1 = g_cs1;
    const float cs0 = g_cs0;
    const float rng = g_rng;

    const int wrow0 = (blockIdx.x * 8 + wid) * 32;
    const float4* __restrict__ xin  = reinterpret_cast<const float4*>(x);
    float2*       __restrict__ out2 = reinterpret_cast<float2*>(out);

    #pragma unroll
    for (int k = 0; k < 4; k++) {
        // lane t holds (row = 8k + t>>2, group = t&3); quantize + byte-pack
        float4 v = xin[(wrow0 + 8 * k) * 4 + t];
        unsigned q0 = quant4(v.x, cs1, cs0);
        unsigned q1 = quant4(v.y, cs1, cs0);
        unsigned q2 = quant4(v.z, cs1, cs0);
        unsigned q3 = quant4(v.w, cs1, cs0);
        unsigned q  = __byte_perm(__byte_perm(q0, q1, 0x0040),
                                  __byte_perm(q2, q3, 0x0040), 0x5410);

        #pragma unroll
        for (int h = 0; h < 4; h++) {
            // lane t computes local row r = 2h + (t>>4); gather its 4 groups
            int r   = 2 * h + (t >> 4);
            int src = r * 4;
            unsigned nq0 = __shfl_sync(0xffffffffu, q, src + 0);
            unsigned nq1 = __shfl_sync(0xffffffffu, q, src + 1);
            unsigned nq2 = __shfl_sync(0xffffffffu, q, src + 2);
            unsigned nq3 = __shfl_sync(0xffffffffu, q, src + 3);

            float2 res;
            float* rp = reinterpret_cast<float*>(&res);
            const float* bp = reinterpret_cast<const float*>(&BIAS);
            #pragma unroll
            for (int jj = 0; jj < 2; jj++) {
                const unsigned* wp = reinterpret_cast<const unsigned*>(&WP[jj]);
                const unsigned* wm = reinterpret_cast<const unsigned*>(&WM[jj]);

                // u = y*17 + 128, rt lives in byte1 (one dp4a, no IMAD)
                unsigned up0 = __dp4a(nq0, wp[0], 128u), um0 = __dp4a(nq0, wm[0], 128u);
                unsigned up1 = __dp4a(nq1, wp[1], 128u), um1 = __dp4a(nq1, wm[1], 128u);
                unsigned up2 = __dp4a(nq2, wp[2], 128u), um2 = __dp4a(nq2, wm[2], 128u);
                unsigned up3 = __dp4a(nq3, wp[3], 128u), um3 = __dp4a(nq3, wm[3], 128u);

                // {rt_p, 0, rt_m, 0} and {0, rt_p, 0, rt_m}
                unsigned p0 = __byte_perm(up0, um0, 0x7531);
                unsigned p1 = __byte_perm(up1, um1, 0x5713);
                unsigned p2 = __byte_perm(up2, um2, 0x7531);
                unsigned p3 = __byte_perm(up3, um3, 0x5713);

                unsigned V = (p0 + p1) + (p2 + p3);   // byte lanes, max 16 each
                // signed dp4a: +p bytes, -m bytes, acc = float magic 2^23+2^22
                int Sb = __dp4a((int)V, (int)0xFFFF0101u, (int)0x4B400000);
                float Sf = __int_as_float(Sb) - 12582912.0f;   // exact S
                rp[jj] = fmaf(Sf, rng, bp[jj]);
            }
            // warp = 2 rows x 128B contiguous -> coalesced STG.64
            out2[(wrow0 + 8 * k + r) * 16 + oc2] = res;
        }
    }
}

extern "C" void kernel_launch(void* const* d_in, const int* in_sizes, int n_in,
                              void* d_out, int out_size) {
    const float* x      = (const float*)d_in[0];
    const float* weight = (const float*)d_in[1];
    // d_in[2] = scale (unused in forward)
    const float* in_max = (const float*)d_in[3];
    const float* in_min = (const float*)d_in[4];
    float* out = (float*)d_out;

    int B = in_sizes[0] / IN_DIM;   // 2,097,152

    prep_kernel<<<1, 32>>>(weight, in_max, in_min);

    int blocks = B / BLOCK;         // 256 rows per block (8 warps x 32 rows)
    quantlinear_kernel<<<blocks, BLOCK>>>(x, out);
}

// round 9
// speedup vs baseline: 1.5856x; 1.0610x over previous
#include <cuda_runtime.h>
#include <cstdint>

#define IN_DIM  16
#define OUT_DIM 32
#define BLOCK   256

// Launch-invariant precomputed state (written by prep kernel each launch).
// Weight planes pre-scaled by 17 so dp4a(nq, w17, 128) = y*17+128 directly
// (max 60*17+128 = 1148; byte1 = round(y/15) exactly for y in [0,60]).
__device__ uint4  g_wp17[OUT_DIM];  // plus-plane  bytes {0,17}
__device__ uint4  g_wm17[OUT_DIM];  // minus-plane bytes {0,17}
__device__ float  g_bias[OUT_DIM];  // in_min * sum_i sign(w[o,i])
__device__ float  g_cs1;            // 1 / rng
__device__ float  g_cs0;            // -in_min / rng
__device__ float  g_rng;            // in_max - in_min

__global__ void prep_kernel(const float* __restrict__ weight,
                            const float* __restrict__ in_max_p,
                            const float* __restrict__ in_min_p) {
    int o = threadIdx.x;
    float in_min = in_min_p[0];
    float rng = in_max_p[0] - in_min;
    if (o == 0) {
        g_rng = rng;
        g_cs1 = 1.0f / rng;
        g_cs0 = -in_min / rng;
    }
    if (o < OUT_DIM) {
        unsigned p[4] = {0u, 0u, 0u, 0u};
        unsigned m[4] = {0u, 0u, 0u, 0u};
        int S = 0;
        #pragma unroll
        for (int i = 0; i < IN_DIM; i++) {
            float wf = weight[o * IN_DIM + i];
            int s = (wf > 0.0f) - (wf < 0.0f);
            S += s;
            int g = i >> 2, k = i & 3;
            if (s > 0) p[g] |= 17u << (8 * k);
            if (s < 0) m[g] |= 17u << (8 * k);
        }
        g_wp17[o] = make_uint4(p[0], p[1], p[2], p[3]);
        g_wm17[o] = make_uint4(m[0], m[1], m[2], m[3]);
        g_bias[o] = in_min * (float)S;
    }
}

// Magic-bias quant: byte0 of fma(sat(fma(v,cs1,cs0)), 15, 2^23) is
// round(15*sat(f)) in [0,15] (RNE, identical to FMUL+F2I.RN). 2 FFMA total.
__device__ __forceinline__ unsigned quantb(float v, float cs1, float cs0) {
    float f = __saturatef(fmaf(v, cs1, cs0));            // FFMA.SAT
    return __float_as_uint(fmaf(f, 15.0f, 8388608.0f));  // FFMA (magic 2^23)
}

__global__ __launch_bounds__(BLOCK, 4)
void quantlinear_kernel(const float* __restrict__ x,
                        float* __restrict__ out) {
    // per-warp double-buffered q-word slab: 8 warps x 2 bufs x 32 words
    __shared__ __align__(16) unsigned s_q[8][2][32];

    const int t   = threadIdx.x & 31;
    const int wid = threadIdx.x >> 5;
    const int oc2 = t & 15;            // output float2-chunk owned by this lane

    // ---- per-lane persistent weights + bias (coalesced one-time loads) ----
    uint4 WP[2], WM[2];
    #pragma unroll
    for (int jj = 0; jj < 2; jj++) {
        WP[jj] = g_wp17[oc2 * 2 + jj];
        WM[jj] = g_wm17[oc2 * 2 + jj];
    }
    const float2 BIAS = reinterpret_cast<const float2*>(g_bias)[oc2];
    const float cs1 = g_cs1;
    const float cs0 = g_cs0;
    const float rng = g_rng;

    const int wrow0 = (blockIdx.x * 8 + wid) * 32;
    const float4* __restrict__ xin  = reinterpret_cast<const float4*>(x);
    float2*       __restrict__ out2 = reinterpret_cast<float2*>(out);

    #pragma unroll
    for (int k = 0; k < 4; k++) {
        // lane t holds (row = 8k + t>>2, group = t&3); quantize + byte-pack
        float4 v = xin[(wrow0 + 8 * k) * 4 + t];
        unsigned b0 = quantb(v.x, cs1, cs0);
        unsigned b1 = quantb(v.y, cs1, cs0);
        unsigned b2 = quantb(v.z, cs1, cs0);
        unsigned b3 = quantb(v.w, cs1, cs0);
        unsigned q  = __byte_perm(__byte_perm(b0, b1, 0x0040),
                                  __byte_perm(b2, b3, 0x0040), 0x5410);

        // stage warp's 32 q-words; double buffer removes WAR sync
        s_q[wid][k & 1][t] = q;
        __syncwarp();

        #pragma unroll
        for (int h = 0; h < 4; h++) {
            // lane t computes local row r = 2h + (t>>4); one LDS.128 fetches
            // its 4 group words (16 lanes broadcast same 16B line)
            int r = 2 * h + (t >> 4);
            uint4 NQ = *reinterpret_cast<const uint4*>(&s_q[wid][k & 1][r * 4]);

            float2 res;
            float* rp = reinterpret_cast<float*>(&res);
            const float* bp = reinterpret_cast<const float*>(&BIAS);
            #pragma unroll
            for (int jj = 0; jj < 2; jj++) {
                const unsigned* wp = reinterpret_cast<const unsigned*>(&WP[jj]);
                const unsigned* wm = reinterpret_cast<const unsigned*>(&WM[jj]);

                // u = y*17 + 128; rt = byte1(u)
                unsigned up0 = __dp4a(NQ.x, wp[0], 128u), um0 = __dp4a(NQ.x, wm[0], 128u);
                unsigned up1 = __dp4a(NQ.y, wp[1], 128u), um1 = __dp4a(NQ.y, wm[1], 128u);
                unsigned up2 = __dp4a(NQ.z, wp[2], 128u), um2 = __dp4a(NQ.z, wm[2], 128u);
                unsigned up3 = __dp4a(NQ.w, wp[3], 128u), um3 = __dp4a(NQ.w, wm[3], 128u);

                // {rt_p, 0, rt_m, 0} and {0, rt_p, 0, rt_m}
                unsigned p0 = __byte_perm(up0, um0, 0x7531);
                unsigned p1 = __byte_perm(up1, um1, 0x5713);
                unsigned p2 = __byte_perm(up2, um2, 0x7531);
                unsigned p3 = __byte_perm(up3, um3, 0x5713);

                unsigned V = (p0 + p1) + (p2 + p3);   // byte lanes, max 8 each
                // signed dp4a: +p bytes, -m bytes, acc = float magic 2^23+2^22
                int Sb = __dp4a((int)V, (int)0xFFFF0101u, (int)0x4B400000);
                float Sf = __int_as_float(Sb) - 12582912.0f;   // exact S
                rp[jj] = fmaf(Sf, rng, bp[jj]);
            }
            // warp = 2 rows x 128B contiguous -> coalesced STG.64
            out2[(wrow0 + 8 * k + r) * 16 + oc2] = res;
        }
    }
}

extern "C" void kernel_launch(void* const* d_in, const int* in_sizes, int n_in,
                              void* d_out, int out_size) {
    const float* x      = (const float*)d_in[0];
    const float* weight = (const float*)d_in[1];
    // d_in[2] = scale (unused in forward)
    const float* in_max = (const float*)d_in[3];
    const float* in_min = (const float*)d_in[4];
    float* out = (float*)d_out;

    int B = in_sizes[0] / IN_DIM;   // 2,097,152

    prep_kernel<<<1, 32>>>(weight, in_max, in_min);

    int blocks = B / BLOCK;         // 256 rows per block (8 warps x 32 rows)
    quantlinear_kernel<<<blocks, BLOCK>>>(x, out);
}

// round 10
// speedup vs baseline: 1.5879x; 1.0014x over previous
#include <cuda_runtime.h>
#include <cstdint>

#define IN_DIM  16
#define OUT_DIM 32
#define BLOCK   256

// Magic-bias quant: byte0 of fma(sat(fma(v,cs1,cs0)), 15, 2^23) is
// round(15*sat(f)) in [0,15] (RNE, identical to FMUL+F2I.RN).
__device__ __forceinline__ unsigned quantb(float v, float cs1, float cs0) {
    float f = __saturatef(fmaf(v, cs1, cs0));            // FFMA.SAT
    return __float_as_uint(fmaf(f, 15.0f, 8388608.0f));  // FFMA (magic 2^23)
}

// Weight planes pre-scaled by 17 so dp4a(nq, w17, 128) = y*17+128 directly
// (max 60*17+128 = 1148; byte1 = round(y/15) exactly for y in [0,60]).
// round is odd on the attainable set (no exact halves), so
// terms = rt(yp) - rt(ym); PRMT packs rt_p in bytes{0,1}, rt_m in bytes{2,3};
// bytes accumulate carry-free; one signed dp4a (sel {+1,+1,-1,-1}, acc
// 0x4B400000) yields float-bits of (12582912 + S) directly (no I2F).

__global__ __launch_bounds__(BLOCK, 4)
void quantlinear_kernel(const float* __restrict__ x,
                        const float* __restrict__ weight,
                        const float* __restrict__ in_max_p,
                        const float* __restrict__ in_min_p,
                        float* __restrict__ out) {
    __shared__ __align__(16) uint4 s_wp17[OUT_DIM];
    __shared__ __align__(16) uint4 s_wm17[OUT_DIM];
    __shared__ __align__(16) float s_bias[OUT_DIM];
    // per-warp double-buffered q-word slab: 8 warps x 2 bufs x 32 words
    __shared__ __align__(16) unsigned s_q[8][2][32];

    const int t   = threadIdx.x & 31;
    const int wid = threadIdx.x >> 5;
    const int oc2 = t & 15;            // output float2-chunk owned by this lane

    // ---- fused prep: warp 0 builds w17/bias tables (one output per lane) --
    const float in_min = in_min_p[0];
    const float rng    = in_max_p[0] - in_min;
    const float cs1    = 1.0f / rng;
    const float cs0    = -in_min * cs1;

    if (threadIdx.x < OUT_DIM) {
        int o = threadIdx.x;
        unsigned p[4] = {0u, 0u, 0u, 0u};
        unsigned m[4] = {0u, 0u, 0u, 0u};
        int S = 0;
        #pragma unroll
        for (int i = 0; i < IN_DIM; i++) {
            float wf = weight[o * IN_DIM + i];
            int s = (wf > 0.0f) - (wf < 0.0f);
            S += s;
            int g = i >> 2, k = i & 3;
            if (s > 0) p[g] |= 17u << (8 * k);
            if (s < 0) m[g] |= 17u << (8 * k);
        }
        s_wp17[o] = make_uint4(p[0], p[1], p[2], p[3]);
        s_wm17[o] = make_uint4(m[0], m[1], m[2], m[3]);
        s_bias[o] = in_min * (float)S;
    }
    __syncthreads();

    // ---- per-lane persistent weights + bias ---------------------------------
    uint4 WP[2], WM[2];
    #pragma unroll
    for (int jj = 0; jj < 2; jj++) {
        WP[jj] = s_wp17[oc2 * 2 + jj];
        WM[jj] = s_wm17[oc2 * 2 + jj];
    }
    const float2 BIAS = reinterpret_cast<const float2*>(s_bias)[oc2];

    const int wrow0 = (blockIdx.x * 8 + wid) * 32;
    const float4* __restrict__ xin  = reinterpret_cast<const float4*>(x);
    float2*       __restrict__ out2 = reinterpret_cast<float2*>(out);

    #pragma unroll
    for (int k = 0; k < 4; k++) {
        // lane t holds (row = 8k + t>>2, group = t&3); quantize + byte-pack
        float4 v = xin[(wrow0 + 8 * k) * 4 + t];
        unsigned b0 = quantb(v.x, cs1, cs0);
        unsigned b1 = quantb(v.y, cs1, cs0);
        unsigned b2 = quantb(v.z, cs1, cs0);
        unsigned b3 = quantb(v.w, cs1, cs0);
        unsigned q  = __byte_perm(__byte_perm(b0, b1, 0x0040),
                                  __byte_perm(b2, b3, 0x0040), 0x5410);

        // stage warp's 32 q-words; double buffer removes WAR sync
        s_q[wid][k & 1][t] = q;
        __syncwarp();

        #pragma unroll
        for (int h = 0; h < 4; h++) {
            // lane t computes local row r = 2h + (t>>4); one LDS.128 fetches
            // its 4 group words (16 lanes broadcast same 16B line)
            int r = 2 * h + (t >> 4);
            uint4 NQ = *reinterpret_cast<const uint4*>(&s_q[wid][k & 1][r * 4]);

            float2 res;
            float* rp = reinterpret_cast<float*>(&res);
            const float* bp = reinterpret_cast<const float*>(&BIAS);
            #pragma unroll
            for (int jj = 0; jj < 2; jj++) {
                const unsigned* wp = reinterpret_cast<const unsigned*>(&WP[jj]);
                const unsigned* wm = reinterpret_cast<const unsigned*>(&WM[jj]);

                // u = y*17 + 128; rt = byte1(u)
                unsigned up0 = __dp4a(NQ.x, wp[0], 128u), um0 = __dp4a(NQ.x, wm[0], 128u);
                unsigned up1 = __dp4a(NQ.y, wp[1], 128u), um1 = __dp4a(NQ.y, wm[1], 128u);
                unsigned up2 = __dp4a(NQ.z, wp[2], 128u), um2 = __dp4a(NQ.z, wm[2], 128u);
                unsigned up3 = __dp4a(NQ.w, wp[3], 128u), um3 = __dp4a(NQ.w, wm[3], 128u);

                // {rt_p, 0, rt_m, 0} and {0, rt_p, 0, rt_m}
                unsigned p0 = __byte_perm(up0, um0, 0x7531);
                unsigned p1 = __byte_perm(up1, um1, 0x5713);
                unsigned p2 = __byte_perm(up2, um2, 0x7531);
                unsigned p3 = __byte_perm(up3, um3, 0x5713);

                unsigned V = (p0 + p1) + (p2 + p3);   // byte lanes, max 16 each
                // signed dp4a: +p bytes, -m bytes, acc = float magic 2^23+2^22
                int Sb = __dp4a((int)V, (int)0xFFFF0101u, (int)0x4B400000);
                float Sf = __int_as_float(Sb) - 12582912.0f;   // exact S
                rp[jj] = fmaf(Sf, rng, bp[jj]);
            }
            // warp = 2 rows x 128B contiguous -> coalesced STG.64
            out2[(wrow0 + 8 * k + r) * 16 + oc2] = res;
        }
    }
}

extern "C" void kernel_launch(void* const* d_in, const int* in_sizes, int n_in,
                              void* d_out, int out_size) {
    const float* x      = (const float*)d_in[0];
    const float* weight = (const float*)d_in[1];
    // d_in[2] = scale (unused in forward)
    const float* in_max = (const float*)d_in[3];
    const float* in_min = (const float*)d_in[4];
    float* out = (float*)d_out;

    int B = in_sizes[0] / IN_DIM;   // 2,097,152

    int blocks = B / BLOCK;         // 256 rows per block (8 warps x 32 rows)
    quantlinear_kernel<<<blocks, BLOCK>>>(x, weight, in_max, in_min, out);
}